// round 16
// baseline (speedup 1.0000x reference)
#include <cuda_runtime.h>
#include <cstdint>

typedef unsigned long long ull;

// Problem constants
#define B_   64
#define T_   1024
#define IN_  512
#define H_   512
#define G4H  2048
#define M_   (B_ * T_)                 // 65536 rows for the input GEMM
#define YSZ  ((size_t)B_ * T_ * H_)    // 33554432 y1 elements
#define HB   (H_ * B_)                 // 32768

// -------- scratch (static device globals; no allocation allowed) ----------
__device__ float g_xz[(size_t)M_ * G4H];   // xz for current layer [B,T,4H]
__device__ float g_y0[(size_t)M_ * H_];    // layer-0 output [B,T,H]
__device__ float g_h[2][2][HB];            // [layer][slot][k*64+m], h TRANSPOSED [H][B]
__device__ unsigned g_bar;                 // grid barrier counter

// -------- packed f32x2 helpers (Blackwell dual-fp32 pipe) -----------------
__device__ __forceinline__ ull ffma2(ull a, ull b, ull c) {
    ull d;
    asm("fma.rn.f32x2 %0, %1, %2, %3;" : "=l"(d) : "l"(a), "l"(b), "l"(c));
    return d;
}
__device__ __forceinline__ ull dup2(float x) {
    ull d;
    asm("mov.b64 %0, {%1, %1};" : "=l"(d) : "f"(x));
    return d;
}
__device__ __forceinline__ float2 unpk(ull v) {
    float lo, hi;
    asm("mov.b64 {%0, %1}, %2;" : "=f"(lo), "=f"(hi) : "l"(v));
    return make_float2(lo, hi);
}
// L2-coherent 16B load (bypass L1: h slots are rewritten by other SMs)
__device__ __forceinline__ void ldcg_u64x2(const void* p, ull& a, ull& b) {
    asm volatile("ld.global.cg.v2.u64 {%0, %1}, [%2];"
                 : "=l"(a), "=l"(b) : "l"(p));
}

// ===================== input-projection GEMM ==============================
// C[M,2048] = A[M,512] * W[512,2048]
// Tile 256x64, thread tile 16m x 4n (acc[8][4]): 32 FFMA2 per 6 LDS.128 ->
// FMA-bound with deep per-thread ILP.   (R15, proven)
#define BM 256
#define BN 64
#define BK 16

__global__ __launch_bounds__(256, 2) void gemm_xw(const float* __restrict__ A,
                                                  const float* __restrict__ W,
                                                  float* __restrict__ C) {
    __shared__ __align__(16) float As[BK * BM];   // transposed A tile (16 KB)
    __shared__ __align__(16) ull   Bsd[BK * BN];  // B tile dup'd f32x2 (8 KB)

    const int tid = threadIdx.x;
    const int tx = tid & 15;
    const int ty = tid >> 4;
    const int m0 = ty * 16;          // 16 rows (8 f32x2 pairs)
    const int n0 = tx * 4;           // 4 cols
    const long gm0 = (long)blockIdx.y * BM;
    const int  gn0 = blockIdx.x * BN;

    const int bkr = tid >> 4;        // B staging: k-row
    const int bnq = tid & 15;        // B staging: n-quad

    ull acc[8][4];
#pragma unroll
    for (int i = 0; i < 8; i++)
#pragma unroll
        for (int j = 0; j < 4; j++) acc[i][j] = 0ull;

    float4 pa0 = *(const float4*)(A + (gm0 + tid) * 512 + 0);
    float4 pa1 = *(const float4*)(A + (gm0 + tid) * 512 + 4);
    float4 pa2 = *(const float4*)(A + (gm0 + tid) * 512 + 8);
    float4 pa3 = *(const float4*)(A + (gm0 + tid) * 512 + 12);
    float4 pb  = *(const float4*)(W + (long)bkr * G4H + gn0 + bnq * 4);
    {
        As[(0 * 4 + 0) * BM + tid] = pa0.x;
        As[(0 * 4 + 1) * BM + tid] = pa0.y;
        As[(0 * 4 + 2) * BM + tid] = pa0.z;
        As[(0 * 4 + 3) * BM + tid] = pa0.w;
        As[(1 * 4 + 0) * BM + tid] = pa1.x;
        As[(1 * 4 + 1) * BM + tid] = pa1.y;
        As[(1 * 4 + 2) * BM + tid] = pa1.z;
        As[(1 * 4 + 3) * BM + tid] = pa1.w;
        As[(2 * 4 + 0) * BM + tid] = pa2.x;
        As[(2 * 4 + 1) * BM + tid] = pa2.y;
        As[(2 * 4 + 2) * BM + tid] = pa2.z;
        As[(2 * 4 + 3) * BM + tid] = pa2.w;
        As[(3 * 4 + 0) * BM + tid] = pa3.x;
        As[(3 * 4 + 1) * BM + tid] = pa3.y;
        As[(3 * 4 + 2) * BM + tid] = pa3.z;
        As[(3 * 4 + 3) * BM + tid] = pa3.w;
        ull* bd = Bsd + bkr * BN + bnq * 4;
        bd[0] = dup2(pb.x); bd[1] = dup2(pb.y);
        bd[2] = dup2(pb.z); bd[3] = dup2(pb.w);
    }
    __syncthreads();

    for (int k0b = 0; k0b < 32; k0b++) {
        const int knext = (k0b + 1) * BK;
        if (k0b < 31) {
            pa0 = *(const float4*)(A + (gm0 + tid) * 512 + knext);
            pa1 = *(const float4*)(A + (gm0 + tid) * 512 + knext + 4);
            pa2 = *(const float4*)(A + (gm0 + tid) * 512 + knext + 8);
            pa3 = *(const float4*)(A + (gm0 + tid) * 512 + knext + 12);
            pb  = *(const float4*)(W + (long)(knext + bkr) * G4H + gn0 + bnq * 4);
        }

#pragma unroll
        for (int kk = 0; kk < BK; kk++) {
            const ulonglong2* ap = (const ulonglong2*)(As + kk * BM + m0);
            ulonglong2 A01 = ap[0], A23 = ap[1], A45 = ap[2], A67 = ap[3];
            const ulonglong2* bp = (const ulonglong2*)(Bsd + kk * BN + n0);
            ulonglong2 B01 = bp[0], B23 = bp[1];
            ull b0 = B01.x, b1 = B01.y, b2 = B23.x, b3 = B23.y;
            acc[0][0] = ffma2(A01.x, b0, acc[0][0]);
            acc[0][1] = ffma2(A01.x, b1, acc[0][1]);
            acc[0][2] = ffma2(A01.x, b2, acc[0][2]);
            acc[0][3] = ffma2(A01.x, b3, acc[0][3]);
            acc[1][0] = ffma2(A01.y, b0, acc[1][0]);
            acc[1][1] = ffma2(A01.y, b1, acc[1][1]);
            acc[1][2] = ffma2(A01.y, b2, acc[1][2]);
            acc[1][3] = ffma2(A01.y, b3, acc[1][3]);
            acc[2][0] = ffma2(A23.x, b0, acc[2][0]);
            acc[2][1] = ffma2(A23.x, b1, acc[2][1]);
            acc[2][2] = ffma2(A23.x, b2, acc[2][2]);
            acc[2][3] = ffma2(A23.x, b3, acc[2][3]);
            acc[3][0] = ffma2(A23.y, b0, acc[3][0]);
            acc[3][1] = ffma2(A23.y, b1, acc[3][1]);
            acc[3][2] = ffma2(A23.y, b2, acc[3][2]);
            acc[3][3] = ffma2(A23.y, b3, acc[3][3]);
            acc[4][0] = ffma2(A45.x, b0, acc[4][0]);
            acc[4][1] = ffma2(A45.x, b1, acc[4][1]);
            acc[4][2] = ffma2(A45.x, b2, acc[4][2]);
            acc[4][3] = ffma2(A45.x, b3, acc[4][3]);
            acc[5][0] = ffma2(A45.y, b0, acc[5][0]);
            acc[5][1] = ffma2(A45.y, b1, acc[5][1]);
            acc[5][2] = ffma2(A45.y, b2, acc[5][2]);
            acc[5][3] = ffma2(A45.y, b3, acc[5][3]);
            acc[6][0] = ffma2(A67.x, b0, acc[6][0]);
            acc[6][1] = ffma2(A67.x, b1, acc[6][1]);
            acc[6][2] = ffma2(A67.x, b2, acc[6][2]);
            acc[6][3] = ffma2(A67.x, b3, acc[6][3]);
            acc[7][0] = ffma2(A67.y, b0, acc[7][0]);
            acc[7][1] = ffma2(A67.y, b1, acc[7][1]);
            acc[7][2] = ffma2(A67.y, b2, acc[7][2]);
            acc[7][3] = ffma2(A67.y, b3, acc[7][3]);
        }

        if (k0b < 31) {
            __syncthreads();
            As[(0 * 4 + 0) * BM + tid] = pa0.x;
            As[(0 * 4 + 1) * BM + tid] = pa0.y;
            As[(0 * 4 + 2) * BM + tid] = pa0.z;
            As[(0 * 4 + 3) * BM + tid] = pa0.w;
            As[(1 * 4 + 0) * BM + tid] = pa1.x;
            As[(1 * 4 + 1) * BM + tid] = pa1.y;
            As[(1 * 4 + 2) * BM + tid] = pa1.z;
            As[(1 * 4 + 3) * BM + tid] = pa1.w;
            As[(2 * 4 + 0) * BM + tid] = pa2.x;
            As[(2 * 4 + 1) * BM + tid] = pa2.y;
            As[(2 * 4 + 2) * BM + tid] = pa2.z;
            As[(2 * 4 + 3) * BM + tid] = pa2.w;
            As[(3 * 4 + 0) * BM + tid] = pa3.x;
            As[(3 * 4 + 1) * BM + tid] = pa3.y;
            As[(3 * 4 + 2) * BM + tid] = pa3.z;
            As[(3 * 4 + 3) * BM + tid] = pa3.w;
            ull* bd = Bsd + bkr * BN + bnq * 4;
            bd[0] = dup2(pb.x); bd[1] = dup2(pb.y);
            bd[2] = dup2(pb.z); bd[3] = dup2(pb.w);
            __syncthreads();
        }
    }

#pragma unroll
    for (int mp = 0; mp < 8; mp++) {
#pragma unroll
        for (int c = 0; c < 4; c++) {
            float2 v = unpk(acc[mp][c]);
            long row = gm0 + m0 + 2 * mp;
            C[row * G4H + gn0 + n0 + c]       = v.x;
            C[(row + 1) * G4H + gn0 + n0 + c] = v.y;
        }
    }
}

// ===================== persistent LSTM layer ==============================
// 128 CTAs (1/SM) x 512 threads (4 warps/SMSP). CTA j owns hidden units
// [4j,4j+4) = 16 gate cols. Thread tile = 16 cols x 4 batch rows, 32-way K
// split (16 k each): h still read EXACTLY ONCE per CTA (128KB/step), but
// twice the warps to hide LDS/LDG latency. Single-counter barrier (R6).
#define PBS   66                                  // padded pbuf row stride
#define WD_BYTES (512 * 16 * 8)                   // 65536
#define PB_BYTES (32 * 16 * PBS * 4)              // 135168
#define LSM_BYTES (WD_BYTES + PB_BYTES)           // 200704
#define NCTA 128

__global__ __launch_bounds__(512, 1) void lstm_layer(
    const float* __restrict__ xz,     // [B,T,4H]
    const float* __restrict__ Wh,     // [512,2048]
    const float* __restrict__ bias,   // [2048]
    float* __restrict__ hs0,          // h slot 0, [H][B]
    float* __restrict__ hs1,          // h slot 1, [H][B]
    float* __restrict__ y,            // [B,T,H]
    float* __restrict__ hfin,         // [B,H]
    float* __restrict__ cfin)         // [B,H]
{
    extern __shared__ char smem[];
    ull*   wdup = (ull*)smem;                   // [512][16] duplicated Wh cols
    float* pbuf = (float*)(smem + WD_BYTES);    // [32 ks][16 c][PBS]

    const int tid = threadIdx.x;
    const int hu0 = blockIdx.x * 4;

    // ---- one-time: load this CTA's Wh slice, duplicated for f32x2 ----
    for (int idx = tid; idx < 512 * 16; idx += 512) {
        int k = idx >> 4, c = idx & 15;
        wdup[idx] = dup2(Wh[(long)k * G4H + (c >> 2) * 512 + hu0 + (c & 3)]);
    }

    // ---- roles ----
    const int mg = tid & 15;         // GEMM: 16 m-groups of 4 rows
    const int ks = tid >> 4;         // GEMM: 32-way K split (16 k each)
    const int m0 = mg * 4;
    const int m  = (tid >> 2) & 63;  // gate pass: batch row (tid<256)
    const int u  = tid & 3;          // gate pass: local unit
    const bool gact = tid < 256;

    float bi = 0.f, bf = 0.f, bg = 0.f, bo = 0.f;
    const float* xzp = xz;
    if (gact) {
        bi = bias[hu0 + u];
        bf = bias[512 + hu0 + u];
        bg = bias[1024 + hu0 + u];
        bo = bias[1536 + hu0 + u];
        xzp = xz + (size_t)m * T_ * G4H + hu0 + u;
    }
    float creg = 0.f;

    float* hslot[2] = { hs0, hs1 };
    __syncthreads();

    // prefetch xz for t = 0
    float x_i = 0.f, x_f = 0.f, x_g = 0.f, x_o = 0.f;
    if (gact) { x_i = xzp[0]; x_f = xzp[512]; x_g = xzp[1024]; x_o = xzp[1536]; }

    for (int t = 0; t < T_; t++) {
        ull acc[2][16];
#pragma unroll
        for (int c = 0; c < 16; c++) { acc[0][c] = 0ull; acc[1][c] = 0ull; }

        if (t > 0) {
            const float* hin = hslot[(t + 1) & 1];   // slot written at t-1
            const float* hp  = hin + (ks * 16) * 64 + m0;
            const ull*   wr  = wdup + (ks * 16) * 16;

            // 4-deep h prefetch pipeline
            ull ph[4][2];
#pragma unroll
            for (int j = 0; j < 4; j++)
                ldcg_u64x2(hp + j * 64, ph[j][0], ph[j][1]);

#pragma unroll 8
            for (int k = 0; k < 16; k++) {
                ull h01 = ph[k & 3][0], h23 = ph[k & 3][1];
                if (k + 4 < 16)
                    ldcg_u64x2(hp + (k + 4) * 64, ph[k & 3][0], ph[k & 3][1]);
                const ulonglong2* w2 = (const ulonglong2*)(wr + k * 16);
                ulonglong2 w01 = w2[0], w23 = w2[1], w45 = w2[2], w67 = w2[3];
                ulonglong2 w89 = w2[4], wab = w2[5], wcd = w2[6], wef = w2[7];
                acc[0][0]  = ffma2(h01, w01.x, acc[0][0]);
                acc[1][0]  = ffma2(h23, w01.x, acc[1][0]);
                acc[0][1]  = ffma2(h01, w01.y, acc[0][1]);
                acc[1][1]  = ffma2(h23, w01.y, acc[1][1]);
                acc[0][2]  = ffma2(h01, w23.x, acc[0][2]);
                acc[1][2]  = ffma2(h23, w23.x, acc[1][2]);
                acc[0][3]  = ffma2(h01, w23.y, acc[0][3]);
                acc[1][3]  = ffma2(h23, w23.y, acc[1][3]);
                acc[0][4]  = ffma2(h01, w45.x, acc[0][4]);
                acc[1][4]  = ffma2(h23, w45.x, acc[1][4]);
                acc[0][5]  = ffma2(h01, w45.y, acc[0][5]);
                acc[1][5]  = ffma2(h23, w45.y, acc[1][5]);
                acc[0][6]  = ffma2(h01, w67.x, acc[0][6]);
                acc[1][6]  = ffma2(h23, w67.x, acc[1][6]);
                acc[0][7]  = ffma2(h01, w67.y, acc[0][7]);
                acc[1][7]  = ffma2(h23, w67.y, acc[1][7]);
                acc[0][8]  = ffma2(h01, w89.x, acc[0][8]);
                acc[1][8]  = ffma2(h23, w89.x, acc[1][8]);
                acc[0][9]  = ffma2(h01, w89.y, acc[0][9]);
                acc[1][9]  = ffma2(h23, w89.y, acc[1][9]);
                acc[0][10] = ffma2(h01, wab.x, acc[0][10]);
                acc[1][10] = ffma2(h23, wab.x, acc[1][10]);
                acc[0][11] = ffma2(h01, wab.y, acc[0][11]);
                acc[1][11] = ffma2(h23, wab.y, acc[1][11]);
                acc[0][12] = ffma2(h01, wcd.x, acc[0][12]);
                acc[1][12] = ffma2(h23, wcd.x, acc[1][12]);
                acc[0][13] = ffma2(h01, wcd.y, acc[0][13]);
                acc[1][13] = ffma2(h23, wcd.y, acc[1][13]);
                acc[0][14] = ffma2(h01, wef.x, acc[0][14]);
                acc[1][14] = ffma2(h23, wef.x, acc[1][14]);
                acc[0][15] = ffma2(h01, wef.y, acc[0][15]);
                acc[1][15] = ffma2(h23, wef.y, acc[1][15]);
            }
        }

        __syncthreads();   // previous step's pbuf reads are done
#pragma unroll
        for (int c = 0; c < 16; c++) {
            *(ull*)&pbuf[(ks * 16 + c) * PBS + m0]     = acc[0][c];
            *(ull*)&pbuf[(ks * 16 + c) * PBS + m0 + 2] = acc[1][c];
        }
        __syncthreads();

        float hn = 0.f;
        if (gact) {
            // ---- K-split reduction + gates (thread = (m, u)) ----
            float zi = bi + x_i, zf = bf + x_f, zg = bg + x_g, zo = bo + x_o;
#pragma unroll
            for (int s = 0; s < 32; s++) {
                const float* pr = pbuf + (s * 16 + u) * PBS + m;
                zi += pr[0];
                zf += pr[4 * PBS];
                zg += pr[8 * PBS];
                zo += pr[12 * PBS];
            }

            float ig  = 1.f / (1.f + __expf(-zi));
            float fg  = 1.f / (1.f + __expf(-zf));
            float gg  = tanhf(zg);
            float ogt = 1.f / (1.f + __expf(-zo));

            creg = fg * creg + ig * gg;
            hn   = ogt * tanhf(creg);

            hslot[t & 1][(hu0 + u) * 64 + m] = hn;
            y[((size_t)m * T_ + t) * H_ + hu0 + u] = hn;
        }

        if (t == T_ - 1) {
            if (gact) {
                hfin[m * H_ + hu0 + u] = hn;
                cfin[m * H_ + hu0 + u] = creg;
            }
        } else {
            // grid barrier: arrive (release) -> prefetch xz(t+1) -> wait
            __syncthreads();   // all h stores of this CTA issued
            if (tid == 0)
                asm volatile("red.release.gpu.global.add.u32 [%0], %1;"
                             :: "l"(&g_bar), "r"(1u) : "memory");
            if (gact) {
                const float* xp = xzp + (size_t)(t + 1) * G4H;
                x_i = xp[0]; x_f = xp[512]; x_g = xp[1024]; x_o = xp[1536];
            }
            if (tid == 0) {
                unsigned target = (unsigned)(t + 1) * NCTA, v;
                do {
                    asm volatile("ld.acquire.gpu.global.u32 %0, [%1];"
                                 : "=r"(v) : "l"(&g_bar) : "memory");
                } while (v < target);
            }
            __syncthreads();
        }
    }
}

// ===================== launch =============================================
extern "C" void kernel_launch(void* const* d_in, const int* in_sizes, int n_in,
                              void* d_out, int out_size) {
    const float* x   = (const float*)d_in[0];
    const float* Wx0 = (const float*)d_in[1];
    const float* Wh0 = (const float*)d_in[2];
    const float* b0  = (const float*)d_in[3];
    const float* Wx1 = (const float*)d_in[4];
    const float* Wh1 = (const float*)d_in[5];
    const float* b1  = (const float*)d_in[6];
    float* out = (float*)d_out;

    float *xz, *y0, *hb;
    unsigned* barp;
    cudaGetSymbolAddress((void**)&xz, g_xz);
    cudaGetSymbolAddress((void**)&y0, g_y0);
    cudaGetSymbolAddress((void**)&hb, g_h);
    cudaGetSymbolAddress((void**)&barp, g_bar);

    cudaFuncSetAttribute(lstm_layer, cudaFuncAttributeMaxDynamicSharedMemorySize,
                         LSM_BYTES);

    dim3 gg(G4H / BN, M_ / BM);  // (32, 256)

    // Layer 0
    cudaMemsetAsync(barp, 0, sizeof(unsigned));
    gemm_xw<<<gg, 256>>>(x, Wx0, xz);
    lstm_layer<<<NCTA, 512, LSM_BYTES>>>(xz, Wh0, b0,
                                         hb, hb + HB,
                                         y0,
                                         out + YSZ,            // h_final[0]
                                         out + YSZ + 2 * HB);  // c_final[0]

    // Layer 1 (reuse xz scratch)
    cudaMemsetAsync(barp, 0, sizeof(unsigned));
    gemm_xw<<<gg, 256>>>(y0, Wx1, xz);
    lstm_layer<<<NCTA, 512, LSM_BYTES>>>(xz, Wh1, b1,
                                         hb + 2 * HB, hb + 3 * HB,
                                         out,
                                         out + YSZ + HB,       // h_final[1]
                                         out + YSZ + 3 * HB);  // c_final[1]
}

// round 17
// speedup vs baseline: 1.2228x; 1.2228x over previous
#include <cuda_runtime.h>
#include <cstdint>

typedef unsigned long long ull;

// Problem constants
#define B_   64
#define T_   1024
#define IN_  512
#define H_   512
#define G4H  2048
#define M_   (B_ * T_)                 // 65536 rows for the input GEMM
#define YSZ  ((size_t)B_ * T_ * H_)    // 33554432 y1 elements
#define HB   (H_ * B_)                 // 32768

// -------- scratch (static device globals; no allocation allowed) ----------
__device__ float g_xz[(size_t)M_ * G4H];              // xz [B,T,4H]
__device__ float g_y0[(size_t)M_ * H_];               // layer output [B,T,H]
__device__ __align__(256) float g_ytmp[(size_t)T_ * HB];  // [T][H][B]: y + h exchange
__device__ unsigned g_bar;                            // grid barrier counter

// -------- packed f32x2 helpers (Blackwell dual-fp32 pipe) -----------------
__device__ __forceinline__ ull ffma2(ull a, ull b, ull c) {
    ull d;
    asm("fma.rn.f32x2 %0, %1, %2, %3;" : "=l"(d) : "l"(a), "l"(b), "l"(c));
    return d;
}
__device__ __forceinline__ ull dup2(float x) {
    ull d;
    asm("mov.b64 %0, {%1, %1};" : "=l"(d) : "f"(x));
    return d;
}
__device__ __forceinline__ float2 unpk(ull v) {
    float lo, hi;
    asm("mov.b64 {%0, %1}, %2;" : "=f"(lo), "=f"(hi) : "l"(v));
    return make_float2(lo, hi);
}
// L2-coherent 16B load (bypass L1: h buffer is rewritten by other SMs)
__device__ __forceinline__ void ldcg_u64x2(const void* p, ull& a, ull& b) {
    asm volatile("ld.global.cg.v2.u64 {%0, %1}, [%2];"
                 : "=l"(a), "=l"(b) : "l"(p));
}

// ===================== input-projection GEMM (R15, proven) ================
// C[M,2048] = A[M,512] * W[512,2048]
#define BM 256
#define BN 64
#define BK 16

__global__ __launch_bounds__(256, 2) void gemm_xw(const float* __restrict__ A,
                                                  const float* __restrict__ W,
                                                  float* __restrict__ C) {
    __shared__ __align__(16) float As[BK * BM];   // transposed A tile (16 KB)
    __shared__ __align__(16) ull   Bsd[BK * BN];  // B tile dup'd f32x2 (8 KB)

    const int tid = threadIdx.x;
    const int tx = tid & 15;
    const int ty = tid >> 4;
    const int m0 = ty * 16;
    const int n0 = tx * 4;
    const long gm0 = (long)blockIdx.y * BM;
    const int  gn0 = blockIdx.x * BN;

    const int bkr = tid >> 4;
    const int bnq = tid & 15;

    ull acc[8][4];
#pragma unroll
    for (int i = 0; i < 8; i++)
#pragma unroll
        for (int j = 0; j < 4; j++) acc[i][j] = 0ull;

    float4 pa0 = *(const float4*)(A + (gm0 + tid) * 512 + 0);
    float4 pa1 = *(const float4*)(A + (gm0 + tid) * 512 + 4);
    float4 pa2 = *(const float4*)(A + (gm0 + tid) * 512 + 8);
    float4 pa3 = *(const float4*)(A + (gm0 + tid) * 512 + 12);
    float4 pb  = *(const float4*)(W + (long)bkr * G4H + gn0 + bnq * 4);
    {
        As[(0 * 4 + 0) * BM + tid] = pa0.x;
        As[(0 * 4 + 1) * BM + tid] = pa0.y;
        As[(0 * 4 + 2) * BM + tid] = pa0.z;
        As[(0 * 4 + 3) * BM + tid] = pa0.w;
        As[(1 * 4 + 0) * BM + tid] = pa1.x;
        As[(1 * 4 + 1) * BM + tid] = pa1.y;
        As[(1 * 4 + 2) * BM + tid] = pa1.z;
        As[(1 * 4 + 3) * BM + tid] = pa1.w;
        As[(2 * 4 + 0) * BM + tid] = pa2.x;
        As[(2 * 4 + 1) * BM + tid] = pa2.y;
        As[(2 * 4 + 2) * BM + tid] = pa2.z;
        As[(2 * 4 + 3) * BM + tid] = pa2.w;
        As[(3 * 4 + 0) * BM + tid] = pa3.x;
        As[(3 * 4 + 1) * BM + tid] = pa3.y;
        As[(3 * 4 + 2) * BM + tid] = pa3.z;
        As[(3 * 4 + 3) * BM + tid] = pa3.w;
        ull* bd = Bsd + bkr * BN + bnq * 4;
        bd[0] = dup2(pb.x); bd[1] = dup2(pb.y);
        bd[2] = dup2(pb.z); bd[3] = dup2(pb.w);
    }
    __syncthreads();

    for (int k0b = 0; k0b < 32; k0b++) {
        const int knext = (k0b + 1) * BK;
        if (k0b < 31) {
            pa0 = *(const float4*)(A + (gm0 + tid) * 512 + knext);
            pa1 = *(const float4*)(A + (gm0 + tid) * 512 + knext + 4);
            pa2 = *(const float4*)(A + (gm0 + tid) * 512 + knext + 8);
            pa3 = *(const float4*)(A + (gm0 + tid) * 512 + knext + 12);
            pb  = *(const float4*)(W + (long)(knext + bkr) * G4H + gn0 + bnq * 4);
        }

#pragma unroll
        for (int kk = 0; kk < BK; kk++) {
            const ulonglong2* ap = (const ulonglong2*)(As + kk * BM + m0);
            ulonglong2 A01 = ap[0], A23 = ap[1], A45 = ap[2], A67 = ap[3];
            const ulonglong2* bp = (const ulonglong2*)(Bsd + kk * BN + n0);
            ulonglong2 B01 = bp[0], B23 = bp[1];
            ull b0 = B01.x, b1 = B01.y, b2 = B23.x, b3 = B23.y;
            acc[0][0] = ffma2(A01.x, b0, acc[0][0]);
            acc[0][1] = ffma2(A01.x, b1, acc[0][1]);
            acc[0][2] = ffma2(A01.x, b2, acc[0][2]);
            acc[0][3] = ffma2(A01.x, b3, acc[0][3]);
            acc[1][0] = ffma2(A01.y, b0, acc[1][0]);
            acc[1][1] = ffma2(A01.y, b1, acc[1][1]);
            acc[1][2] = ffma2(A01.y, b2, acc[1][2]);
            acc[1][3] = ffma2(A01.y, b3, acc[1][3]);
            acc[2][0] = ffma2(A23.x, b0, acc[2][0]);
            acc[2][1] = ffma2(A23.x, b1, acc[2][1]);
            acc[2][2] = ffma2(A23.x, b2, acc[2][2]);
            acc[2][3] = ffma2(A23.x, b3, acc[2][3]);
            acc[3][0] = ffma2(A23.y, b0, acc[3][0]);
            acc[3][1] = ffma2(A23.y, b1, acc[3][1]);
            acc[3][2] = ffma2(A23.y, b2, acc[3][2]);
            acc[3][3] = ffma2(A23.y, b3, acc[3][3]);
            acc[4][0] = ffma2(A45.x, b0, acc[4][0]);
            acc[4][1] = ffma2(A45.x, b1, acc[4][1]);
            acc[4][2] = ffma2(A45.x, b2, acc[4][2]);
            acc[4][3] = ffma2(A45.x, b3, acc[4][3]);
            acc[5][0] = ffma2(A45.y, b0, acc[5][0]);
            acc[5][1] = ffma2(A45.y, b1, acc[5][1]);
            acc[5][2] = ffma2(A45.y, b2, acc[5][2]);
            acc[5][3] = ffma2(A45.y, b3, acc[5][3]);
            acc[6][0] = ffma2(A67.x, b0, acc[6][0]);
            acc[6][1] = ffma2(A67.x, b1, acc[6][1]);
            acc[6][2] = ffma2(A67.x, b2, acc[6][2]);
            acc[6][3] = ffma2(A67.x, b3, acc[6][3]);
            acc[7][0] = ffma2(A67.y, b0, acc[7][0]);
            acc[7][1] = ffma2(A67.y, b1, acc[7][1]);
            acc[7][2] = ffma2(A67.y, b2, acc[7][2]);
            acc[7][3] = ffma2(A67.y, b3, acc[7][3]);
        }

        if (k0b < 31) {
            __syncthreads();
            As[(0 * 4 + 0) * BM + tid] = pa0.x;
            As[(0 * 4 + 1) * BM + tid] = pa0.y;
            As[(0 * 4 + 2) * BM + tid] = pa0.z;
            As[(0 * 4 + 3) * BM + tid] = pa0.w;
            As[(1 * 4 + 0) * BM + tid] = pa1.x;
            As[(1 * 4 + 1) * BM + tid] = pa1.y;
            As[(1 * 4 + 2) * BM + tid] = pa1.z;
            As[(1 * 4 + 3) * BM + tid] = pa1.w;
            As[(2 * 4 + 0) * BM + tid] = pa2.x;
            As[(2 * 4 + 1) * BM + tid] = pa2.y;
            As[(2 * 4 + 2) * BM + tid] = pa2.z;
            As[(2 * 4 + 3) * BM + tid] = pa2.w;
            As[(3 * 4 + 0) * BM + tid] = pa3.x;
            As[(3 * 4 + 1) * BM + tid] = pa3.y;
            As[(3 * 4 + 2) * BM + tid] = pa3.z;
            As[(3 * 4 + 3) * BM + tid] = pa3.w;
            ull* bd = Bsd + bkr * BN + bnq * 4;
            bd[0] = dup2(pb.x); bd[1] = dup2(pb.y);
            bd[2] = dup2(pb.z); bd[3] = dup2(pb.w);
            __syncthreads();
        }
    }

#pragma unroll
    for (int mp = 0; mp < 8; mp++) {
#pragma unroll
        for (int c = 0; c < 4; c++) {
            float2 v = unpk(acc[mp][c]);
            long row = gm0 + m0 + 2 * mp;
            C[row * G4H + gn0 + n0 + c]       = v.x;
            C[(row + 1) * G4H + gn0 + n0 + c] = v.y;
        }
    }
}

// ===================== persistent LSTM layer (R13 base) ===================
// 128 CTAs (1/SM) x 256 threads. CTA j owns hidden units [4j,4j+4) = 16 gate
// cols. Thread tile = 16 cols x 4 batch rows, 16-way K split. h from L2
// (ld.cg, 4-deep pipeline). ONLY change vs R13: h/y stores merged into ONE
// coalesced store to ytmp[t][h][b] (8 L2 lines/CTA-step instead of 264), so
// the barrier release drains almost nothing. ytmp doubles as the h-exchange
// buffer (t-indexed -> no ping-pong) and the y record (transposed later).
#define PBS   66                                  // padded pbuf row stride
#define WD_BYTES (512 * 16 * 8)                   // 65536
#define PB_BYTES (16 * 16 * PBS * 4)              // 67584
#define LSM_BYTES (WD_BYTES + PB_BYTES)           // 133120
#define NCTA 128

__global__ __launch_bounds__(256, 1) void lstm_layer(
    const float* __restrict__ xz,     // [B,T,4H]
    const float* __restrict__ Wh,     // [512,2048]
    const float* __restrict__ bias,   // [2048]
    float* __restrict__ ytmp,         // [T][H][B]
    float* __restrict__ hfin,         // [B,H]
    float* __restrict__ cfin)         // [B,H]
{
    extern __shared__ char smem[];
    ull*   wdup = (ull*)smem;                   // [512][16] duplicated Wh cols
    float* pbuf = (float*)(smem + WD_BYTES);    // [16 ks][16 c][PBS]

    const int tid = threadIdx.x;
    const int hu0 = blockIdx.x * 4;

    // ---- one-time: load this CTA's Wh slice, duplicated for f32x2 ----
    for (int idx = tid; idx < 512 * 16; idx += 256) {
        int k = idx >> 4, c = idx & 15;
        wdup[idx] = dup2(Wh[(long)k * G4H + (c >> 2) * 512 + hu0 + (c & 3)]);
    }

    // ---- roles ----
    const int mg = tid & 15;         // GEMM: 16 m-groups of 4 rows
    const int ks = tid >> 4;         // GEMM: 16-way K split (32 k each)
    const int m0 = mg * 4;
    const int m  = tid >> 2;         // gate pass: batch row
    const int u  = tid & 3;          // gate pass: local unit

    const float bi = bias[hu0 + u];
    const float bf = bias[512 + hu0 + u];
    const float bg = bias[1024 + hu0 + u];
    const float bo = bias[1536 + hu0 + u];
    float creg = 0.f;
    const float* xzp = xz + (size_t)m * T_ * G4H + hu0 + u;

    __syncthreads();

    // prefetch xz for t = 0
    float x_i = xzp[0], x_f = xzp[512], x_g = xzp[1024], x_o = xzp[1536];

    for (int t = 0; t < T_; t++) {
        ull acc[2][16];
#pragma unroll
        for (int c = 0; c < 16; c++) { acc[0][c] = 0ull; acc[1][c] = 0ull; }

        if (t > 0) {
            const float* hin = ytmp + (size_t)(t - 1) * HB;   // h(t-1)
            const float* hp  = hin + (ks * 32) * 64 + m0;
            const ull*   wr  = wdup + (ks * 32) * 16;

            // 4-deep h prefetch pipeline
            ull ph[4][2];
#pragma unroll
            for (int j = 0; j < 4; j++)
                ldcg_u64x2(hp + j * 64, ph[j][0], ph[j][1]);

#pragma unroll 8
            for (int k = 0; k < 32; k++) {
                ull h01 = ph[k & 3][0], h23 = ph[k & 3][1];
                if (k + 4 < 32)
                    ldcg_u64x2(hp + (k + 4) * 64, ph[k & 3][0], ph[k & 3][1]);
                const ulonglong2* w2 = (const ulonglong2*)(wr + k * 16);
                ulonglong2 w01 = w2[0], w23 = w2[1], w45 = w2[2], w67 = w2[3];
                ulonglong2 w89 = w2[4], wab = w2[5], wcd = w2[6], wef = w2[7];
                acc[0][0]  = ffma2(h01, w01.x, acc[0][0]);
                acc[1][0]  = ffma2(h23, w01.x, acc[1][0]);
                acc[0][1]  = ffma2(h01, w01.y, acc[0][1]);
                acc[1][1]  = ffma2(h23, w01.y, acc[1][1]);
                acc[0][2]  = ffma2(h01, w23.x, acc[0][2]);
                acc[1][2]  = ffma2(h23, w23.x, acc[1][2]);
                acc[0][3]  = ffma2(h01, w23.y, acc[0][3]);
                acc[1][3]  = ffma2(h23, w23.y, acc[1][3]);
                acc[0][4]  = ffma2(h01, w45.x, acc[0][4]);
                acc[1][4]  = ffma2(h23, w45.x, acc[1][4]);
                acc[0][5]  = ffma2(h01, w45.y, acc[0][5]);
                acc[1][5]  = ffma2(h23, w45.y, acc[1][5]);
                acc[0][6]  = ffma2(h01, w67.x, acc[0][6]);
                acc[1][6]  = ffma2(h23, w67.x, acc[1][6]);
                acc[0][7]  = ffma2(h01, w67.y, acc[0][7]);
                acc[1][7]  = ffma2(h23, w67.y, acc[1][7]);
                acc[0][8]  = ffma2(h01, w89.x, acc[0][8]);
                acc[1][8]  = ffma2(h23, w89.x, acc[1][8]);
                acc[0][9]  = ffma2(h01, w89.y, acc[0][9]);
                acc[1][9]  = ffma2(h23, w89.y, acc[1][9]);
                acc[0][10] = ffma2(h01, wab.x, acc[0][10]);
                acc[1][10] = ffma2(h23, wab.x, acc[1][10]);
                acc[0][11] = ffma2(h01, wab.y, acc[0][11]);
                acc[1][11] = ffma2(h23, wab.y, acc[1][11]);
                acc[0][12] = ffma2(h01, wcd.x, acc[0][12]);
                acc[1][12] = ffma2(h23, wcd.x, acc[1][12]);
                acc[0][13] = ffma2(h01, wcd.y, acc[0][13]);
                acc[1][13] = ffma2(h23, wcd.y, acc[1][13]);
                acc[0][14] = ffma2(h01, wef.x, acc[0][14]);
                acc[1][14] = ffma2(h23, wef.x, acc[1][14]);
                acc[0][15] = ffma2(h01, wef.y, acc[0][15]);
                acc[1][15] = ffma2(h23, wef.y, acc[1][15]);
            }
        }

        __syncthreads();   // previous step's pbuf reads are done
#pragma unroll
        for (int c = 0; c < 16; c++) {
            *(ull*)&pbuf[(ks * 16 + c) * PBS + m0]     = acc[0][c];
            *(ull*)&pbuf[(ks * 16 + c) * PBS + m0 + 2] = acc[1][c];
        }
        __syncthreads();

        // ---- K-split reduction + gates (thread = (m, u)) ----
        float zi = bi + x_i, zf = bf + x_f, zg = bg + x_g, zo = bo + x_o;
#pragma unroll
        for (int s = 0; s < 16; s++) {
            const float* pr = pbuf + (s * 16 + u) * PBS + m;
            zi += pr[0];
            zf += pr[4 * PBS];
            zg += pr[8 * PBS];
            zo += pr[12 * PBS];
        }

        float ig  = 1.f / (1.f + __expf(-zi));
        float fg  = 1.f / (1.f + __expf(-zf));
        float gg  = tanhf(zg);
        float ogt = 1.f / (1.f + __expf(-zo));

        creg = fg * creg + ig * gg;
        float hn = ogt * tanhf(creg);

        // SINGLE coalesced store: y record AND h-exchange source (8 lines)
        ytmp[((size_t)t * 512 + hu0 + u) * 64 + m] = hn;

        if (t == T_ - 1) {
            hfin[m * H_ + hu0 + u] = hn;
            cfin[m * H_ + hu0 + u] = creg;
        } else {
            // grid barrier: arrive (release) -> prefetch xz(t+1) -> wait
            __syncthreads();   // all h stores of this CTA issued
            if (tid == 0)
                asm volatile("red.release.gpu.global.add.u32 [%0], %1;"
                             :: "l"(&g_bar), "r"(1u) : "memory");
            const float* xp = xzp + (size_t)(t + 1) * G4H;
            x_i = xp[0]; x_f = xp[512]; x_g = xp[1024]; x_o = xp[1536];
            if (tid == 0) {
                unsigned target = (unsigned)(t + 1) * NCTA, v;
                do {
                    asm volatile("ld.acquire.gpu.global.u32 %0, [%1];"
                                 : "=r"(v) : "l"(&g_bar) : "memory");
                } while (v < target);
            }
            __syncthreads();
        }
    }
}

// ===================== y transpose: [T][H][B] -> [B][T][H] ================
#define TR_SMEM (512 * 65 * 4)    // 133120

__global__ __launch_bounds__(512) void transpose_y(
    const float* __restrict__ ytmp, float* __restrict__ yout) {
    extern __shared__ float s[];
    const int t = blockIdx.x;
    const int tid = threadIdx.x;
    const float4* src = (const float4*)(ytmp + (size_t)t * HB);
#pragma unroll
    for (int it = 0; it < 16; it++) {
        int lin = (it * 512 + tid) * 4;
        float4 v = src[it * 512 + tid];
        int h = lin >> 6, b = lin & 63;
        float* d = s + h * 65 + b;
        d[0] = v.x; d[1] = v.y; d[2] = v.z; d[3] = v.w;
    }
    __syncthreads();
#pragma unroll 4
    for (int b = 0; b < 64; b++)
        yout[((size_t)b * T_ + t) * H_ + tid] = s[tid * 65 + b];
}

// ===================== launch =============================================
extern "C" void kernel_launch(void* const* d_in, const int* in_sizes, int n_in,
                              void* d_out, int out_size) {
    const float* x   = (const float*)d_in[0];
    const float* Wx0 = (const float*)d_in[1];
    const float* Wh0 = (const float*)d_in[2];
    const float* b0  = (const float*)d_in[3];
    const float* Wx1 = (const float*)d_in[4];
    const float* Wh1 = (const float*)d_in[5];
    const float* b1  = (const float*)d_in[6];
    float* out = (float*)d_out;

    float *xz, *y0, *yt;
    unsigned* barp;
    cudaGetSymbolAddress((void**)&xz, g_xz);
    cudaGetSymbolAddress((void**)&y0, g_y0);
    cudaGetSymbolAddress((void**)&yt, g_ytmp);
    cudaGetSymbolAddress((void**)&barp, g_bar);

    cudaFuncSetAttribute(lstm_layer, cudaFuncAttributeMaxDynamicSharedMemorySize,
                         LSM_BYTES);
    cudaFuncSetAttribute(transpose_y, cudaFuncAttributeMaxDynamicSharedMemorySize,
                         TR_SMEM);

    dim3 gg(G4H / BN, M_ / BM);  // (32, 256)

    // Layer 0
    cudaMemsetAsync(barp, 0, sizeof(unsigned));
    gemm_xw<<<gg, 256>>>(x, Wx0, xz);
    lstm_layer<<<NCTA, 256, LSM_BYTES>>>(xz, Wh0, b0, yt,
                                         out + YSZ,            // h_final[0]
                                         out + YSZ + 2 * HB);  // c_final[0]
    transpose_y<<<T_, 512, TR_SMEM>>>(yt, y0);

    // Layer 1 (reuse xz and ytmp scratch)
    cudaMemsetAsync(barp, 0, sizeof(unsigned));
    gemm_xw<<<gg, 256>>>(y0, Wx1, xz);
    lstm_layer<<<NCTA, 256, LSM_BYTES>>>(xz, Wh1, b1, yt,
                                         out + YSZ + HB,       // h_final[1]
                                         out + YSZ + 3 * HB);  // c_final[1]
    transpose_y<<<T_, 512, TR_SMEM>>>(yt, out);
}